// round 1
// baseline (speedup 1.0000x reference)
#include <cuda_runtime.h>
#include <cuda_bf16.h>
#include <math.h>

// ---------------------------------------------------------------------------
// Problem constants
// ---------------------------------------------------------------------------
#define BATCH    2
#define SEQ      2048
#define DIM      2048
#define NHEADS   16
#define NKV      4
#define HD       128
#define M_ROWS   (BATCH * SEQ)          // 4096
#define QCOLS    (NHEADS * HD)          // 2048
#define KVCOLS   (NKV * HD)             // 512

// ---------------------------------------------------------------------------
// Device scratch (no cudaMalloc allowed)
// ---------------------------------------------------------------------------
__device__ float g_Q[(size_t)M_ROWS * QCOLS];    // 33.5 MB
__device__ float g_K[(size_t)M_ROWS * KVCOLS];   //  8.4 MB
__device__ float g_V[(size_t)M_ROWS * KVCOLS];   //  8.4 MB
__device__ float g_O[(size_t)M_ROWS * QCOLS];    // 33.5 MB

// ---------------------------------------------------------------------------
// SGEMM: C[M,N] = A[M,K] @ B[K,N], all row-major fp32.
// 128x128 block tile, BK=16, 256 threads, 8x8 per-thread microtile.
// ---------------------------------------------------------------------------
__global__ __launch_bounds__(256, 2)
void sgemm128(const float* __restrict__ A, const float* __restrict__ B,
              float* __restrict__ C, int M, int N, int K) {
    __shared__ float As[16][132];   // transposed A tile, padded (132) for banks
    __shared__ float Bs[16][128];

    const int tid = threadIdx.x;
    const int tx = tid & 15;        // 0..15 -> N direction
    const int ty = tid >> 4;        // 0..15 -> M direction
    const int row0 = blockIdx.y * 128;
    const int col0 = blockIdx.x * 128;

    float acc[8][8];
#pragma unroll
    for (int i = 0; i < 8; i++)
#pragma unroll
        for (int j = 0; j < 8; j++) acc[i][j] = 0.f;

    for (int k0 = 0; k0 < K; k0 += 16) {
        // Load A tile (128 rows x 16 cols) -> transposed into As
#pragma unroll
        for (int l = 0; l < 2; l++) {
            int f  = tid + l * 256;          // 0..511 float4 index
            int r  = f >> 2;                 // 0..127
            int c4 = f & 3;                  // 0..3
            float4 v = *(const float4*)(A + (size_t)(row0 + r) * K + k0 + c4 * 4);
            As[c4 * 4 + 0][r] = v.x;
            As[c4 * 4 + 1][r] = v.y;
            As[c4 * 4 + 2][r] = v.z;
            As[c4 * 4 + 3][r] = v.w;
        }
        // Load B tile (16 rows x 128 cols)
#pragma unroll
        for (int l = 0; l < 2; l++) {
            int f  = tid + l * 256;
            int r  = f >> 5;                 // 0..15
            int c4 = f & 31;                 // 0..31
            *(float4*)&Bs[r][c4 * 4] =
                *(const float4*)(B + (size_t)(k0 + r) * N + col0 + c4 * 4);
        }
        __syncthreads();

#pragma unroll
        for (int kk = 0; kk < 16; kk++) {
            float a[8], b[8];
            *(float4*)(a)     = *(float4*)&As[kk][ty * 8];
            *(float4*)(a + 4) = *(float4*)&As[kk][ty * 8 + 4];
            *(float4*)(b)     = *(float4*)&Bs[kk][tx * 8];
            *(float4*)(b + 4) = *(float4*)&Bs[kk][tx * 8 + 4];
#pragma unroll
            for (int i = 0; i < 8; i++)
#pragma unroll
                for (int j = 0; j < 8; j++)
                    acc[i][j] += a[i] * b[j];
        }
        __syncthreads();
    }

#pragma unroll
    for (int i = 0; i < 8; i++) {
        float* crow = C + (size_t)(row0 + ty * 8 + i) * N + col0 + tx * 8;
        float4 v0 = make_float4(acc[i][0], acc[i][1], acc[i][2], acc[i][3]);
        float4 v1 = make_float4(acc[i][4], acc[i][5], acc[i][6], acc[i][7]);
        *(float4*)(crow)     = v0;
        *(float4*)(crow + 4) = v1;
    }
}

// ---------------------------------------------------------------------------
// RoPE (interleaved pairs), in place on [M_ROWS][n_heads*128]
// ---------------------------------------------------------------------------
__global__ void rope_kernel(float* __restrict__ X, const float* __restrict__ fc,
                            const float* __restrict__ fs, int n_heads, int total) {
    int idx = blockIdx.x * blockDim.x + threadIdx.x;
    if (idx >= total) return;
    int pair = idx & 63;                       // 0..63
    int h    = (idx >> 6) % n_heads;
    int m    = idx / (64 * n_heads);
    int s    = m & (SEQ - 1);
    float c  = fc[s * 64 + pair];
    float sn = fs[s * 64 + pair];
    float2* p = (float2*)(X + (size_t)m * (n_heads * HD) + h * HD + pair * 2);
    float2 v = *p;
    float xr = v.x, xi = v.y;
    p->x = xr * c - xi * sn;
    p->y = xr * sn + xi * c;
}

// ---------------------------------------------------------------------------
// Flash attention (causal, GQA). One block per (b*h, q-tile of 64 rows).
// 256 threads: tx = tid&15 (cols), ty = tid>>4 (4-row groups).
// smem: Qs[64][128] | Kst[128][68] (K transposed) | Vs[64][128] | Ps[64][64]
// ---------------------------------------------------------------------------
#define ATT_SMEM_FLOATS (64*128 + 128*68 + 64*128 + 64*64)
#define ATT_SMEM_BYTES  (ATT_SMEM_FLOATS * 4)

__global__ __launch_bounds__(256, 1)
void attn_kernel(const float* __restrict__ Q, const float* __restrict__ K,
                 const float* __restrict__ V, float* __restrict__ O) {
    extern __shared__ float sm[];
    float* Qs  = sm;                    // [64][128]
    float* Kst = sm + 64 * 128;         // [128][68]
    float* Vs  = Kst + 128 * 68;        // [64][128]
    float* Ps  = Vs + 64 * 128;         // [64][64]

    const int tid = threadIdx.x;
    const int tx  = tid & 15;
    const int ty  = tid >> 4;
    const int i   = (gridDim.x - 1) - blockIdx.x;   // long tiles first
    const int bh  = blockIdx.y;
    const int b   = bh >> 4;
    const int h   = bh & 15;
    const int g   = h >> 2;                         // kv head
    const float scale = 0.08838834764831845f;       // 1/sqrt(128)

    // Load Q tile (pre-scaled)
    const size_t qbase = ((size_t)(b * SEQ + i * 64)) * QCOLS + h * HD;
#pragma unroll
    for (int l = 0; l < 8; l++) {
        int f = tid + l * 256;          // 0..2047 float4 index
        int r = f >> 5, c4 = f & 31;
        float4 v = *(const float4*)(Q + qbase + (size_t)r * QCOLS + c4 * 4);
        v.x *= scale; v.y *= scale; v.z *= scale; v.w *= scale;
        *(float4*)&Qs[r * 128 + c4 * 4] = v;
    }

    float o[4][8];
    float mrow[4], lrow[4];
#pragma unroll
    for (int r = 0; r < 4; r++) {
        mrow[r] = -1e30f; lrow[r] = 0.f;
#pragma unroll
        for (int c = 0; c < 8; c++) o[r][c] = 0.f;
    }

    for (int j = 0; j <= i; j++) {
        __syncthreads();   // previous O-accum done before K/V overwrite
        const size_t kbase = ((size_t)(b * SEQ + j * 64)) * KVCOLS + g * HD;
#pragma unroll
        for (int l = 0; l < 8; l++) {
            int f = tid + l * 256;
            int r = f >> 5, c4 = f & 31;
            float4 kv = *(const float4*)(K + kbase + (size_t)r * KVCOLS + c4 * 4);
            Kst[(c4 * 4 + 0) * 68 + r] = kv.x;
            Kst[(c4 * 4 + 1) * 68 + r] = kv.y;
            Kst[(c4 * 4 + 2) * 68 + r] = kv.z;
            Kst[(c4 * 4 + 3) * 68 + r] = kv.w;
            *(float4*)&Vs[r * 128 + c4 * 4] =
                *(const float4*)(V + kbase + (size_t)r * KVCOLS + c4 * 4);
        }
        __syncthreads();

        // S tile: rows ty*4+r, cols tx*4+c
        float s[4][4];
#pragma unroll
        for (int r = 0; r < 4; r++)
#pragma unroll
            for (int c = 0; c < 4; c++) s[r][c] = 0.f;

#pragma unroll
        for (int d4 = 0; d4 < 32; d4++) {
            float q[4][4], kk[4][4];
#pragma unroll
            for (int r = 0; r < 4; r++)
                *(float4*)q[r] = *(float4*)&Qs[(ty * 4 + r) * 128 + d4 * 4];
#pragma unroll
            for (int e = 0; e < 4; e++)
                *(float4*)kk[e] = *(float4*)&Kst[(d4 * 4 + e) * 68 + tx * 4];
#pragma unroll
            for (int r = 0; r < 4; r++)
#pragma unroll
                for (int e = 0; e < 4; e++)
#pragma unroll
                    for (int c = 0; c < 4; c++)
                        s[r][c] += q[r][e] * kk[e][c];
        }

        if (j == i) {   // causal mask on diagonal tile
#pragma unroll
            for (int r = 0; r < 4; r++)
#pragma unroll
                for (int c = 0; c < 4; c++)
                    if (tx * 4 + c > ty * 4 + r) s[r][c] = -1e30f;
        }

        // online softmax per row (reduce across 16 tx lanes)
#pragma unroll
        for (int r = 0; r < 4; r++) {
            float mx = fmaxf(fmaxf(s[r][0], s[r][1]), fmaxf(s[r][2], s[r][3]));
#pragma unroll
            for (int off = 8; off >= 1; off >>= 1)
                mx = fmaxf(mx, __shfl_xor_sync(0xffffffffu, mx, off, 16));
            float mnew  = fmaxf(mrow[r], mx);
            float alpha = __expf(mrow[r] - mnew);
            float p0 = __expf(s[r][0] - mnew);
            float p1 = __expf(s[r][1] - mnew);
            float p2 = __expf(s[r][2] - mnew);
            float p3 = __expf(s[r][3] - mnew);
            float sum = p0 + p1 + p2 + p3;
#pragma unroll
            for (int off = 8; off >= 1; off >>= 1)
                sum += __shfl_xor_sync(0xffffffffu, sum, off, 16);
            lrow[r] = lrow[r] * alpha + sum;
            mrow[r] = mnew;
#pragma unroll
            for (int c = 0; c < 8; c++) o[r][c] *= alpha;
            float4 pv = make_float4(p0, p1, p2, p3);
            *(float4*)&Ps[(ty * 4 + r) * 64 + tx * 4] = pv;
        }
        __syncthreads();

        // O += P @ V   (thread owns rows ty*4+r, d-cols tx*8..+7)
#pragma unroll 16
        for (int k = 0; k < 64; k++) {
            float p0 = Ps[(ty * 4 + 0) * 64 + k];
            float p1 = Ps[(ty * 4 + 1) * 64 + k];
            float p2 = Ps[(ty * 4 + 2) * 64 + k];
            float p3 = Ps[(ty * 4 + 3) * 64 + k];
            float4 v0 = *(float4*)&Vs[k * 128 + tx * 8];
            float4 v1 = *(float4*)&Vs[k * 128 + tx * 8 + 4];
            o[0][0] += p0 * v0.x; o[0][1] += p0 * v0.y; o[0][2] += p0 * v0.z; o[0][3] += p0 * v0.w;
            o[0][4] += p0 * v1.x; o[0][5] += p0 * v1.y; o[0][6] += p0 * v1.z; o[0][7] += p0 * v1.w;
            o[1][0] += p1 * v0.x; o[1][1] += p1 * v0.y; o[1][2] += p1 * v0.z; o[1][3] += p1 * v0.w;
            o[1][4] += p1 * v1.x; o[1][5] += p1 * v1.y; o[1][6] += p1 * v1.z; o[1][7] += p1 * v1.w;
            o[2][0] += p2 * v0.x; o[2][1] += p2 * v0.y; o[2][2] += p2 * v0.z; o[2][3] += p2 * v0.w;
            o[2][4] += p2 * v1.x; o[2][5] += p2 * v1.y; o[2][6] += p2 * v1.z; o[2][7] += p2 * v1.w;
            o[3][0] += p3 * v0.x; o[3][1] += p3 * v0.y; o[3][2] += p3 * v0.z; o[3][3] += p3 * v0.w;
            o[3][4] += p3 * v1.x; o[3][5] += p3 * v1.y; o[3][6] += p3 * v1.z; o[3][7] += p3 * v1.w;
        }
    }

    // finalize + write
    const size_t obase = ((size_t)(b * SEQ + i * 64)) * QCOLS + h * HD;
#pragma unroll
    for (int r = 0; r < 4; r++) {
        float inv = 1.0f / lrow[r];
        float4 v0 = make_float4(o[r][0] * inv, o[r][1] * inv, o[r][2] * inv, o[r][3] * inv);
        float4 v1 = make_float4(o[r][4] * inv, o[r][5] * inv, o[r][6] * inv, o[r][7] * inv);
        float* dst = (float*)(O + obase + (size_t)(ty * 4 + r) * QCOLS + tx * 8);
        *(float4*)(dst)     = v0;
        *(float4*)(dst + 4) = v1;
    }
}

// ---------------------------------------------------------------------------
// Launch
// ---------------------------------------------------------------------------
extern "C" void kernel_launch(void* const* d_in, const int* in_sizes, int n_in,
                              void* d_out, int out_size) {
    const float* x    = (const float*)d_in[0];
    const float* fcos = (const float*)d_in[1];
    const float* fsin = (const float*)d_in[2];
    const float* Wq   = (const float*)d_in[3];
    const float* Wk   = (const float*)d_in[4];
    const float* Wv   = (const float*)d_in[5];
    const float* Wo   = (const float*)d_in[6];
    float* out = (float*)d_out;

    float *Qb, *Kb, *Vb, *Ob;
    cudaGetSymbolAddress((void**)&Qb, g_Q);
    cudaGetSymbolAddress((void**)&Kb, g_K);
    cudaGetSymbolAddress((void**)&Vb, g_V);
    cudaGetSymbolAddress((void**)&Ob, g_O);

    cudaFuncSetAttribute(attn_kernel,
                         cudaFuncAttributeMaxDynamicSharedMemorySize,
                         ATT_SMEM_BYTES);

    // QKV projections
    sgemm128<<<dim3(QCOLS / 128, M_ROWS / 128), 256>>>(x, Wq, Qb, M_ROWS, QCOLS, DIM);
    sgemm128<<<dim3(KVCOLS / 128, M_ROWS / 128), 256>>>(x, Wk, Kb, M_ROWS, KVCOLS, DIM);
    sgemm128<<<dim3(KVCOLS / 128, M_ROWS / 128), 256>>>(x, Wv, Vb, M_ROWS, KVCOLS, DIM);

    // RoPE
    {
        int totq = M_ROWS * NHEADS * 64;
        int totk = M_ROWS * NKV * 64;
        rope_kernel<<<(totq + 255) / 256, 256>>>(Qb, fcos, fsin, NHEADS, totq);
        rope_kernel<<<(totk + 255) / 256, 256>>>(Kb, fcos, fsin, NKV, totk);
    }

    // Attention
    attn_kernel<<<dim3(SEQ / 64, BATCH * NHEADS), 256, ATT_SMEM_BYTES>>>(Qb, Kb, Vb, Ob);

    // Output projection
    sgemm128<<<dim3(DIM / 128, M_ROWS / 128), 256>>>(Ob, Wo, out, M_ROWS, DIM, DIM);
}

// round 3
// speedup vs baseline: 2.6886x; 2.6886x over previous
#include <cuda_runtime.h>
#include <cuda_bf16.h>
#include <math.h>
#include <stdint.h>

// ---------------------------------------------------------------------------
// Problem constants
// ---------------------------------------------------------------------------
#define BATCH    2
#define SEQ      2048
#define DIM      2048
#define NHEADS   16
#define NKV      4
#define HD       128
#define M_ROWS   (BATCH * SEQ)          // 4096
#define QCOLS    (NHEADS * HD)          // 2048
#define KVCOLS   (NKV * HD)             // 512

// ---------------------------------------------------------------------------
// Device scratch (no cudaMalloc allowed)
// ---------------------------------------------------------------------------
__device__ float g_Q[(size_t)M_ROWS * QCOLS];
__device__ float g_K[(size_t)M_ROWS * KVCOLS];
__device__ float g_V[(size_t)M_ROWS * KVCOLS];
__device__ float g_O[(size_t)M_ROWS * QCOLS];

// ---------------------------------------------------------------------------
// tf32 helpers
// ---------------------------------------------------------------------------
__device__ __forceinline__ uint32_t f2tf32(float f) {
    uint32_t r;
    asm("cvt.rna.tf32.f32 %0, %1;" : "=r"(r) : "f"(f));
    return r;
}

// D += A*B  (m16n8k8, A row-major, B col-major, fp32 accum)
__device__ __forceinline__ void mma_tf32(float d[4], const uint32_t a[4],
                                         const uint32_t b[2]) {
    asm volatile(
        "mma.sync.aligned.m16n8k8.row.col.f32.tf32.tf32.f32 "
        "{%0,%1,%2,%3}, {%4,%5,%6,%7}, {%8,%9}, {%0,%1,%2,%3};\n"
        : "+f"(d[0]), "+f"(d[1]), "+f"(d[2]), "+f"(d[3])
        : "r"(a[0]), "r"(a[1]), "r"(a[2]), "r"(a[3]), "r"(b[0]), "r"(b[1]));
}

// ---------------------------------------------------------------------------
// tf32 GEMM: C[M,N] = A[M,K] @ B[K,N], row-major fp32 in/out.
// 128x128 block, BK=32, 256 threads (8 warps as 2m x 4n, warp tile 64x32).
// ---------------------------------------------------------------------------
__global__ __launch_bounds__(256)
void gemm_tf32(const float* __restrict__ A, const float* __restrict__ B,
               float* __restrict__ C, int M, int N, int K) {
    __shared__ uint32_t As[128][36];    // [row][k], pad 36 -> frag bank = 4*grp+tig
    __shared__ uint32_t Bs[32][132];    // [k][col], pad 132 -> frag bank = 4*tig+grp

    const int tid  = threadIdx.x;
    const int lane = tid & 31;
    const int wid  = tid >> 5;
    const int wm   = wid >> 2;          // 0..1 (64-row warp tile)
    const int wn   = wid & 3;           // 0..3 (32-col warp tile)
    const int grp  = lane >> 2;
    const int tig  = lane & 3;
    const int row0 = blockIdx.y * 128;
    const int col0 = blockIdx.x * 128;

    float acc[4][4][4];
#pragma unroll
    for (int mf = 0; mf < 4; mf++)
#pragma unroll
        for (int nf = 0; nf < 4; nf++)
#pragma unroll
            for (int e = 0; e < 4; e++) acc[mf][nf][e] = 0.f;

    for (int k0 = 0; k0 < K; k0 += 32) {
#pragma unroll
        for (int l = 0; l < 4; l++) {       // A tile 128x32
            int f = tid + l * 256;          // float4 index 0..1023
            int r = f >> 3, c = (f & 7) * 4;
            float4 v = *(const float4*)(A + (size_t)(row0 + r) * K + k0 + c);
            As[r][c + 0] = f2tf32(v.x);
            As[r][c + 1] = f2tf32(v.y);
            As[r][c + 2] = f2tf32(v.z);
            As[r][c + 3] = f2tf32(v.w);
        }
#pragma unroll
        for (int l = 0; l < 4; l++) {       // B tile 32x128
            int f = tid + l * 256;
            int r = f >> 5, c = (f & 31) * 4;
            float4 v = *(const float4*)(B + (size_t)(k0 + r) * N + col0 + c);
            Bs[r][c + 0] = f2tf32(v.x);
            Bs[r][c + 1] = f2tf32(v.y);
            Bs[r][c + 2] = f2tf32(v.z);
            Bs[r][c + 3] = f2tf32(v.w);
        }
        __syncthreads();

#pragma unroll
        for (int ks = 0; ks < 4; ks++) {
            const int kk = ks * 8;
            uint32_t af[4][4], bf[4][2];
#pragma unroll
            for (int mf = 0; mf < 4; mf++) {
                int r = wm * 64 + mf * 16;
                af[mf][0] = As[r + grp][kk + tig];
                af[mf][1] = As[r + grp + 8][kk + tig];
                af[mf][2] = As[r + grp][kk + tig + 4];
                af[mf][3] = As[r + grp + 8][kk + tig + 4];
            }
#pragma unroll
            for (int nf = 0; nf < 4; nf++) {
                int c = wn * 32 + nf * 8;
                bf[nf][0] = Bs[kk + tig][c + grp];
                bf[nf][1] = Bs[kk + tig + 4][c + grp];
            }
#pragma unroll
            for (int mf = 0; mf < 4; mf++)
#pragma unroll
                for (int nf = 0; nf < 4; nf++)
                    mma_tf32(acc[mf][nf], af[mf], bf[nf]);
        }
        __syncthreads();
    }

#pragma unroll
    for (int mf = 0; mf < 4; mf++) {
#pragma unroll
        for (int nf = 0; nf < 4; nf++) {
            int r = row0 + wm * 64 + mf * 16;
            int c = col0 + wn * 32 + nf * 8 + tig * 2;
            *(float2*)(C + (size_t)(r + grp) * N + c) =
                make_float2(acc[mf][nf][0], acc[mf][nf][1]);
            *(float2*)(C + (size_t)(r + grp + 8) * N + c) =
                make_float2(acc[mf][nf][2], acc[mf][nf][3]);
        }
    }
}

// ---------------------------------------------------------------------------
// RoPE (interleaved pairs), in place on [M_ROWS][n_heads*128]
// ---------------------------------------------------------------------------
__global__ void rope_kernel(float* __restrict__ X, const float* __restrict__ fc,
                            const float* __restrict__ fs, int n_heads, int total) {
    int idx = blockIdx.x * blockDim.x + threadIdx.x;
    if (idx >= total) return;
    int pair = idx & 63;
    int h    = (idx >> 6) % n_heads;
    int m    = idx / (64 * n_heads);
    int s    = m & (SEQ - 1);
    float c  = fc[s * 64 + pair];
    float sn = fs[s * 64 + pair];
    float2* p = (float2*)(X + (size_t)m * (n_heads * HD) + h * HD + pair * 2);
    float2 v = *p;
    p->x = v.x * c - v.y * sn;
    p->y = v.x * sn + v.y * c;
}

// ---------------------------------------------------------------------------
// Flash attention w/ tf32 tensor cores. BQ=BK=64, 256 threads (8 warps).
// S phase: warps 4m x 2n (tile 16x32). PV phase: warps 2m x 4n (tile 32x32).
// Softmax: thread = (row = tid>>2, sub = tid&3), 16 cols each, shfl width 4.
// smem (uint32 units): Qs/Ks/Vs [64][132] tf32 | Ss/Ps [64][68] | alphas | lsum
// ---------------------------------------------------------------------------
#define QP 132
#define SP 68
#define ATT_SMEM_U32 (3 * 64 * QP + 64 * SP + 64 + 64)
#define ATT_SMEM_BYTES (ATT_SMEM_U32 * 4)

__global__ __launch_bounds__(256)
void attn_tc(const float* __restrict__ Q, const float* __restrict__ K,
             const float* __restrict__ V, float* __restrict__ O) {
    extern __shared__ uint32_t sm[];
    uint32_t* Qs = sm;
    uint32_t* Ks = sm + 64 * QP;
    uint32_t* Vs = Ks + 64 * QP;
    uint32_t* Ps = Vs + 64 * QP;       // tf32 probs (post-softmax)
    float*    Ss = (float*)Ps;         // fp32 scores (pre-softmax), same buffer
    float* alphas = (float*)(Ps + 64 * SP);
    float* lsum   = alphas + 64;

    const int tid  = threadIdx.x;
    const int lane = tid & 31;
    const int wid  = tid >> 5;
    const int grp  = lane >> 2;
    const int tig  = lane & 3;
    const int i  = (gridDim.x - 1) - blockIdx.x;    // long tiles first
    const int bh = blockIdx.y;
    const int b  = bh >> 4;
    const int h  = bh & 15;
    const int g  = h >> 2;
    const float scale = 0.08838834764831845f;       // 1/sqrt(128)

    const int swm = wid >> 1, swn = wid & 1;        // S-phase warp coords
    const int pwm = wid >> 2, pwn = wid & 3;        // PV-phase warp coords
    const int srow = tid >> 2, ssub = tid & 3;      // softmax coords

    // Load Q tile (pre-scaled, tf32)
    const size_t qbase = ((size_t)(b * SEQ + i * 64)) * QCOLS + h * HD;
#pragma unroll
    for (int l = 0; l < 8; l++) {
        int f = tid + l * 256;
        int r = f >> 5, c = (f & 31) * 4;
        float4 v = *(const float4*)(Q + qbase + (size_t)r * QCOLS + c);
        Qs[r * QP + c + 0] = f2tf32(v.x * scale);
        Qs[r * QP + c + 1] = f2tf32(v.y * scale);
        Qs[r * QP + c + 2] = f2tf32(v.z * scale);
        Qs[r * QP + c + 3] = f2tf32(v.w * scale);
    }

    float oacc[2][4][4];
#pragma unroll
    for (int mf = 0; mf < 2; mf++)
#pragma unroll
        for (int nf = 0; nf < 4; nf++)
#pragma unroll
            for (int e = 0; e < 4; e++) oacc[mf][nf][e] = 0.f;
    float mrow = -1e30f, lrow = 0.f;

    for (int j = 0; j <= i; j++) {
        __syncthreads();    // protect Ks/Vs/Ps from prior-iter readers
        const size_t kb = ((size_t)(b * SEQ + j * 64)) * KVCOLS + g * HD;
#pragma unroll
        for (int l = 0; l < 8; l++) {
            int f = tid + l * 256;
            int r = f >> 5, c = (f & 31) * 4;
            float4 kv = *(const float4*)(K + kb + (size_t)r * KVCOLS + c);
            Ks[r * QP + c + 0] = f2tf32(kv.x);
            Ks[r * QP + c + 1] = f2tf32(kv.y);
            Ks[r * QP + c + 2] = f2tf32(kv.z);
            Ks[r * QP + c + 3] = f2tf32(kv.w);
            float4 vv = *(const float4*)(V + kb + (size_t)r * KVCOLS + c);
            Vs[r * QP + c + 0] = f2tf32(vv.x);
            Vs[r * QP + c + 1] = f2tf32(vv.y);
            Vs[r * QP + c + 2] = f2tf32(vv.z);
            Vs[r * QP + c + 3] = f2tf32(vv.w);
        }
        __syncthreads();

        // ---- S = Q @ K^T (each warp: 16x32 tile) ----
        float sacc[4][4];
#pragma unroll
        for (int nf = 0; nf < 4; nf++)
#pragma unroll
            for (int e = 0; e < 4; e++) sacc[nf][e] = 0.f;

#pragma unroll
        for (int ks = 0; ks < 16; ks++) {
            const int kk = ks * 8;
            uint32_t af[4];
            const int r = swm * 16;
            af[0] = Qs[(r + grp) * QP + kk + tig];
            af[1] = Qs[(r + grp + 8) * QP + kk + tig];
            af[2] = Qs[(r + grp) * QP + kk + tig + 4];
            af[3] = Qs[(r + grp + 8) * QP + kk + tig + 4];
#pragma unroll
            for (int nf = 0; nf < 4; nf++) {
                const int c = swn * 32 + nf * 8;
                uint32_t bf[2];
                bf[0] = Ks[(c + grp) * QP + kk + tig];
                bf[1] = Ks[(c + grp) * QP + kk + tig + 4];
                mma_tf32(sacc[nf], af, bf);
            }
        }
#pragma unroll
        for (int nf = 0; nf < 4; nf++) {
            int r = swm * 16 + grp;
            int c = swn * 32 + nf * 8 + tig * 2;
            *(float2*)&Ss[r * SP + c]       = make_float2(sacc[nf][0], sacc[nf][1]);
            *(float2*)&Ss[(r + 8) * SP + c] = make_float2(sacc[nf][2], sacc[nf][3]);
        }
        __syncthreads();

        // ---- online softmax (row srow, cols ssub*16..+15) ----
        {
            float p[16];
            float mx = -1e30f;
#pragma unroll
            for (int c = 0; c < 16; c++) {
                float s = Ss[srow * SP + ssub * 16 + c];
                if (j == i && (ssub * 16 + c) > srow) s = -1e30f;
                p[c] = s;
                mx = fmaxf(mx, s);
            }
            mx = fmaxf(mx, __shfl_xor_sync(0xffffffffu, mx, 1, 4));
            mx = fmaxf(mx, __shfl_xor_sync(0xffffffffu, mx, 2, 4));
            float mnew = fmaxf(mrow, mx);
            float al   = __expf(mrow - mnew);
            float sum  = 0.f;
#pragma unroll
            for (int c = 0; c < 16; c++) {
                p[c] = __expf(p[c] - mnew);
                sum += p[c];
            }
            sum += __shfl_xor_sync(0xffffffffu, sum, 1, 4);
            sum += __shfl_xor_sync(0xffffffffu, sum, 2, 4);
            lrow = lrow * al + sum;
            mrow = mnew;
            if (ssub == 0) alphas[srow] = al;
#pragma unroll
            for (int c = 0; c < 16; c++)
                Ps[srow * SP + ssub * 16 + c] = f2tf32(p[c]);
        }
        __syncthreads();

        // ---- rescale O, then O += P @ V (each warp: 32x32 tile) ----
#pragma unroll
        for (int mf = 0; mf < 2; mf++) {
            int r = pwm * 32 + mf * 16;
            float alo = alphas[r + grp];
            float ahi = alphas[r + grp + 8];
#pragma unroll
            for (int nf = 0; nf < 4; nf++) {
                oacc[mf][nf][0] *= alo; oacc[mf][nf][1] *= alo;
                oacc[mf][nf][2] *= ahi; oacc[mf][nf][3] *= ahi;
            }
        }
#pragma unroll
        for (int ks = 0; ks < 8; ks++) {
            const int kk = ks * 8;
            uint32_t af[2][4];
#pragma unroll
            for (int mf = 0; mf < 2; mf++) {
                int r = pwm * 32 + mf * 16;
                af[mf][0] = Ps[(r + grp) * SP + kk + tig];
                af[mf][1] = Ps[(r + grp + 8) * SP + kk + tig];
                af[mf][2] = Ps[(r + grp) * SP + kk + tig + 4];
                af[mf][3] = Ps[(r + grp + 8) * SP + kk + tig + 4];
            }
#pragma unroll
            for (int nf = 0; nf < 4; nf++) {
                const int c = pwn * 32 + nf * 8;
                uint32_t bf[2];
                bf[0] = Vs[(kk + tig) * QP + c + grp];
                bf[1] = Vs[(kk + tig + 4) * QP + c + grp];
#pragma unroll
                for (int mf = 0; mf < 2; mf++)
                    mma_tf32(oacc[mf][nf], af[mf], bf);
            }
        }
    }

    if (ssub == 0) lsum[srow] = lrow;
    __syncthreads();

    const size_t obase = ((size_t)(b * SEQ + i * 64)) * QCOLS + h * HD;
#pragma unroll
    for (int mf = 0; mf < 2; mf++) {
        int r = pwm * 32 + mf * 16;
        float ilo = 1.f / lsum[r + grp];
        float ihi = 1.f / lsum[r + grp + 8];
#pragma unroll
        for (int nf = 0; nf < 4; nf++) {
            int c = pwn * 32 + nf * 8 + tig * 2;
            *(float2*)(O + obase + (size_t)(r + grp) * QCOLS + c) =
                make_float2(oacc[mf][nf][0] * ilo, oacc[mf][nf][1] * ilo);
            *(float2*)(O + obase + (size_t)(r + grp + 8) * QCOLS + c) =
                make_float2(oacc[mf][nf][2] * ihi, oacc[mf][nf][3] * ihi);
        }
    }
}

// ---------------------------------------------------------------------------
// Launch
// ---------------------------------------------------------------------------
extern "C" void kernel_launch(void* const* d_in, const int* in_sizes, int n_in,
                              void* d_out, int out_size) {
    const float* x    = (const float*)d_in[0];
    const float* fcos = (const float*)d_in[1];
    const float* fsin = (const float*)d_in[2];
    const float* Wq   = (const float*)d_in[3];
    const float* Wk   = (const float*)d_in[4];
    const float* Wv   = (const float*)d_in[5];
    const float* Wo   = (const float*)d_in[6];
    float* out = (float*)d_out;

    float *Qb, *Kb, *Vb, *Ob;
    cudaGetSymbolAddress((void**)&Qb, g_Q);
    cudaGetSymbolAddress((void**)&Kb, g_K);
    cudaGetSymbolAddress((void**)&Vb, g_V);
    cudaGetSymbolAddress((void**)&Ob, g_O);

    cudaFuncSetAttribute(attn_tc,
                         cudaFuncAttributeMaxDynamicSharedMemorySize,
                         ATT_SMEM_BYTES);

    // QKV projections (tf32 tensor cores)
    gemm_tf32<<<dim3(QCOLS / 128, M_ROWS / 128), 256>>>(x, Wq, Qb, M_ROWS, QCOLS, DIM);
    gemm_tf32<<<dim3(KVCOLS / 128, M_ROWS / 128), 256>>>(x, Wk, Kb, M_ROWS, KVCOLS, DIM);
    gemm_tf32<<<dim3(KVCOLS / 128, M_ROWS / 128), 256>>>(x, Wv, Vb, M_ROWS, KVCOLS, DIM);

    // RoPE
    {
        int totq = M_ROWS * NHEADS * 64;
        int totk = M_ROWS * NKV * 64;
        rope_kernel<<<(totq + 255) / 256, 256>>>(Qb, fcos, fsin, NHEADS, totq);
        rope_kernel<<<(totk + 255) / 256, 256>>>(Kb, fcos, fsin, NKV, totk);
    }

    // Attention (tf32 tensor cores)
    attn_tc<<<dim3(SEQ / 64, BATCH * NHEADS), 256, ATT_SMEM_BYTES>>>(Qb, Kb, Vb, Ob);

    // Output projection
    gemm_tf32<<<dim3(DIM / 128, M_ROWS / 128), 256>>>(Ob, Wo, out, M_ROWS, DIM, DIM);
}